// round 16
// baseline (speedup 1.0000x reference)
#include <cuda_runtime.h>
#include <cuda_bf16.h>

#define N_NODES 50000
#define N_EDGES 1200000
#define DIM 64
#define SCAN_B 49    // ceil(50000/1024)
#define NPB 96       // nodes per block in fused agg+layer
#define TS 97        // transposed shared stride (floats)

// Scratch (allocation-free __device__ globals)
__device__ __align__(16) float g_Henc[N_NODES * DIM];         // layer output H_l (fp32)
__device__ __align__(16) unsigned int g_Hb0[N_NODES * DIM/2]; // bf16x2 gather table (buf 0)
__device__ __align__(16) unsigned int g_Hb1[N_NODES * DIM/2]; // bf16x2 gather table (buf 1)
__device__ __align__(16) int   g_deg [N_NODES];               // out-degree over u
__device__ __align__(16) int   g_cnt [N_NODES];               // in-degree over v
__device__ __align__(16) int   g_rowstart[N_NODES + 1];       // CSR row offsets (by v)
__device__ __align__(16) int2  g_uv  [N_EDGES];               // decoded (u,v)
__device__ __align__(16) int   g_rank[N_EDGES];               // rank of edge within row v
__device__ __align__(16) int   g_csr [N_EDGES];               // u sorted by v
__device__ __align__(16) float g_dis [N_NODES];               // rsqrt(deg+1)
__device__ __align__(16) float g_svs [N_NODES];               // sum_{u in N(v)} dis_u
__device__ __align__(16) float g_Wc  [3 * DIM * DIM];         // composite We@Wu per layer
__device__ __align__(16) float g_c2  [3 * DIM];               // be@Wu per layer
__device__ __align__(16) float g_sum64[DIM];
__device__ __align__(16) int   g_bsum[SCAN_B];                // per-block cnt sums
__device__ int g_is32;   // 1 if edge_index is int32 on device
__device__ int g_done;   // last-block ticket for fused readout

// ---------------------------------------------------------------------------
// Packed f32x2 helpers
__device__ __forceinline__ void ffma2(unsigned long long& d,
                                      unsigned long long a,
                                      unsigned long long b) {
    asm("fma.rn.f32x2 %0, %1, %2, %0;" : "+l"(d) : "l"(a), "l"(b));
}
__device__ __forceinline__ unsigned long long pack2(float lo, float hi) {
    unsigned long long r;
    asm("mov.b64 %0, {%1, %2};" : "=l"(r) : "f"(lo), "f"(hi));
    return r;
}
__device__ __forceinline__ void unpack2(unsigned long long v, float& lo, float& hi) {
    asm("mov.b64 {%0, %1}, %2;" : "=f"(lo), "=f"(hi) : "l"(v));
}

// ---------------------------------------------------------------------------
// Init + weight composition + dtype probe (merged).
__global__ void __launch_bounds__(256) k_init(
    const unsigned long long* __restrict__ ei,
    const float* __restrict__ We0, const float* __restrict__ Be0, const float* __restrict__ Wu0,
    const float* __restrict__ We1, const float* __restrict__ Be1, const float* __restrict__ Wu1,
    const float* __restrict__ We2, const float* __restrict__ Be2, const float* __restrict__ Wu2)
{
    int i = blockIdx.x * 256 + threadIdx.x;
    if (i < N_NODES) { g_deg[i] = 0; g_cnt[i] = 0; g_svs[i] = 0.f; }
    if (i < DIM)     g_sum64[i] = 0.f;
    if (i == 0)      g_done = 0;

    int b = blockIdx.x;
    int t = threadIdx.x;
    if (b == 3) {
        unsigned int any = 0;
        for (int j = t; j < 2048; j += 256)
            any |= (unsigned int)(ei[j] >> 32);
        __shared__ unsigned int s;
        if (t == 0) s = 0u;
        __syncthreads();
        atomicOr(&s, any);
        __syncthreads();
        if (t == 0) g_is32 = (s != 0u) ? 1 : 0;
    } else if (b < 3) {
        const float* We = (b == 0) ? We0 : (b == 1) ? We1 : We2;
        const float* Be = (b == 0) ? Be0 : (b == 1) ? Be1 : Be2;
        const float* Wu = (b == 0) ? Wu0 : (b == 1) ? Wu1 : Wu2;
        __shared__ float sWe[DIM * DIM], sWu[DIM * DIM];
        for (int j = t; j < DIM * DIM; j += 256) { sWe[j] = We[j]; sWu[j] = Wu[j]; }
        __syncthreads();
        for (int o = t; o < DIM * DIM; o += 256) {
            int r = o >> 6, c = o & 63;
            float acc = 0.f;
#pragma unroll 8
            for (int k = 0; k < DIM; k++)
                acc = fmaf(sWe[r * DIM + k], sWu[k * DIM + c], acc);
            g_Wc[b * DIM * DIM + o] = acc;
        }
        if (t < DIM) {
            float acc = 0.f;
#pragma unroll 8
            for (int k = 0; k < DIM; k++)
                acc = fmaf(Be[k], sWu[k * DIM + t], acc);
            g_c2[b * DIM + t] = acc;
        }
    }
}

// Decode edge index -> uv + rank, histogram deg(u)/cnt(v). 2 edges per thread.
__global__ void __launch_bounds__(256) k_prep(const void* __restrict__ eiv) {
    int p = blockIdx.x * 256 + threadIdx.x;       // pair index
    int i = p * 2;
    if (i >= N_EDGES) return;
    int u0, u1, v0, v1;
    if (g_is32) {
        const int2* e = (const int2*)eiv;
        int2 up = e[p];
        int2 vp = ((const int2*)((const int*)eiv + N_EDGES))[p];
        u0 = up.x; u1 = up.y; v0 = vp.x; v1 = vp.y;
    } else {
        const longlong2* e = (const longlong2*)eiv;
        longlong2 up = e[p];
        longlong2 vp = ((const longlong2*)((const long long*)eiv + N_EDGES))[p];
        u0 = (int)up.x; u1 = (int)up.y; v0 = (int)vp.x; v1 = (int)vp.y;
    }
    u0 = min(max(u0, 0), N_NODES - 1); u1 = min(max(u1, 0), N_NODES - 1);
    v0 = min(max(v0, 0), N_NODES - 1); v1 = min(max(v1, 0), N_NODES - 1);
    ((int4*)g_uv)[p] = make_int4(u0, v0, u1, v1);
    atomicAdd(&g_deg[u0], 1);
    atomicAdd(&g_deg[u1], 1);
    int r0 = atomicAdd(&g_cnt[v0], 1);
    int r1 = atomicAdd(&g_cnt[v1], 1);
    ((int2*)g_rank)[p] = make_int2(r0, r1);
}

// Per-block sums of g_cnt; also precompute dis = rsqrt(deg+1)
__global__ void __launch_bounds__(1024) k_bsum() {
    int t = threadIdx.x;
    int i = blockIdx.x * 1024 + t;
    int val = 0;
    if (i < N_NODES) {
        val = g_cnt[i];
        g_dis[i] = rsqrtf((float)g_deg[i] + 1.0f);
    }
#pragma unroll
    for (int o = 16; o; o >>= 1) val += __shfl_xor_sync(0xffffffffu, val, o);
    __shared__ int ws[32];
    if ((t & 31) == 0) ws[t >> 5] = val;
    __syncthreads();
    if (t < 32) {
        int v = ws[t];
#pragma unroll
        for (int o = 16; o; o >>= 1) v += __shfl_xor_sync(0xffffffffu, v, o);
        if (t == 0) g_bsum[blockIdx.x] = v;
    }
}

// Block-local exclusive scan + parallel-loaded global base -> g_rowstart
__global__ void __launch_bounds__(1024) k_scan2() {
    int t = threadIdx.x;
    int b = blockIdx.x;
    int i = b * 1024 + t;
    __shared__ int sbase;
    __shared__ int sb[SCAN_B];
    __shared__ int ws[32];
    if (t < SCAN_B) sb[t] = g_bsum[t];     // parallel load
    __syncthreads();
    if (t == 0) {
        int a = 0;
        for (int j = 0; j < b; j++) a += sb[j];
        sbase = a;
    }
    int orig = (i < N_NODES) ? g_cnt[i] : 0;
    int val = orig;
    int lane = t & 31;
#pragma unroll
    for (int o = 1; o < 32; o <<= 1) {
        int n = __shfl_up_sync(0xffffffffu, val, o);
        if (lane >= o) val += n;
    }
    if (lane == 31) ws[t >> 5] = val;
    __syncthreads();
    if (t < 32) {
        int v = ws[t];
#pragma unroll
        for (int o = 1; o < 32; o <<= 1) {
            int n = __shfl_up_sync(0xffffffffu, v, o);
            if (t >= o) v += n;
        }
        ws[t] = v;
    }
    __syncthreads();
    int woff = (t >= 32) ? ws[(t >> 5) - 1] : 0;
    int excl = sbase + woff + (val - orig);
    if (i < N_NODES) {
        g_rowstart[i] = excl;
        if (i == N_NODES - 1) g_rowstart[N_NODES] = excl + orig;
    }
}

// Merged: CSR fill (blocks < EB) + layer-0 Hb table into buf 0 (blocks >= EB).
#define EB_CONST ((N_EDGES + 255) / 256)
__global__ void __launch_bounds__(256) k_fillhb(const float* __restrict__ X) {
    int b = blockIdx.x;
    int t = threadIdx.x;
    if (b < EB_CONST) {
        int i = b * 256 + t;
        if (i >= N_EDGES) return;
        int2 uv = g_uv[i];
        int pos = g_rowstart[uv.y] + g_rank[i];
        g_csr[pos] = uv.x;
        atomicAdd(&g_svs[uv.y], g_dis[uv.x]);
    } else {
        int idx = (b - EB_CONST) * 256 + t;      // node*16 + c
        if (idx >= N_NODES * 16) return;
        int node = idx >> 4;
        float dis = g_dis[node];
        float4 v = ((const float4*)X)[idx];
        __nv_bfloat162 b0 = __floats2bfloat162_rn(v.x * dis, v.y * dis);
        __nv_bfloat162 b1 = __floats2bfloat162_rn(v.z * dis, v.w * dis);
        ((uint2*)g_Hb0)[idx] = make_uint2(*(unsigned int*)&b0, *(unsigned int*)&b1);
    }
}

// ---------------------------------------------------------------------------
// bf16x2-pair add helper (dis_u pre-folded into Hb)
__device__ __forceinline__ void bf16add(float4& a, uint2 p) {
    float2 lo = __bfloat1622float2(*(__nv_bfloat162*)&p.x);
    float2 hi = __bfloat1622float2(*(__nv_bfloat162*)&p.y);
    a.x += lo.x; a.y += lo.y; a.z += hi.x; a.w += hi.y;
}

// ---------------------------------------------------------------------------
// FUSED agg + layer GEMM, double-buffered gather table.
// rb: read buffer (0/1) for phase-1 gathers; layer writes the OTHER buffer
// (wb = 1-rb) unless final_layer. This removes the cross-block RAW hazard:
// a block's phase-2 writes go to a buffer no concurrent phase-1 reads.
__global__ void __launch_bounds__(256) k_agglayer(
    int l, int use_X, int final_layer, int rb,
    const float* __restrict__ X,
    const float* __restrict__ Bu,
    const float* __restrict__ out_w, const float* __restrict__ out_b,
    float* __restrict__ out)
{
    __shared__ float sAggT[DIM * TS];              // 24832 B
    __shared__ unsigned long long Ws2[2048];       // 16384 B (64 k x 32 pairs)
    __shared__ float B1[64], B2[64];
    __shared__ float ssum[64];
    int tid = threadIdx.x;
    int base = blockIdx.x * NPB;

    // Load W (packed pairs) + biases
    const ulonglong2* W8 = (const ulonglong2*)(g_Wc + l * DIM * DIM);
    ulonglong2* S8 = (ulonglong2*)Ws2;
#pragma unroll
    for (int i = 0; i < 4; i++) S8[tid + 256 * i] = W8[tid + 256 * i];
    if (tid < 64) { B1[tid] = Bu[tid]; B2[tid] = g_c2[l * DIM + tid]; ssum[tid] = 0.f; }

    // ---- Phase 1: aggregation into transposed shared ----
    const uint2* __restrict__ Hb = rb ? (const uint2*)g_Hb1 : (const uint2*)g_Hb0;
    const float* self = use_X ? X : g_Henc;
    int c  = tid & 15;
    int no = tid >> 4;                  // 0..15
#pragma unroll 1
    for (int pass = 0; pass < NPB / 16; pass++) {
        int nl = pass * 16 + no;        // node local 0..95
        int node = base + nl;
        if (node < N_NODES) {
            int s = g_rowstart[node];
            int e = g_rowstart[node + 1];
            float4 a0 = make_float4(0.f, 0.f, 0.f, 0.f);
            float4 a1 = make_float4(0.f, 0.f, 0.f, 0.f);
            float4 a2 = make_float4(0.f, 0.f, 0.f, 0.f);
            float4 a3 = make_float4(0.f, 0.f, 0.f, 0.f);
            int i = s;
            for (; i + 4 <= e; i += 4) {
                int u0 = g_csr[i];
                int u1 = g_csr[i + 1];
                int u2 = g_csr[i + 2];
                int u3 = g_csr[i + 3];
                uint2 p0 = Hb[u0 * 16 + c];
                uint2 p1 = Hb[u1 * 16 + c];
                uint2 p2 = Hb[u2 * 16 + c];
                uint2 p3 = Hb[u3 * 16 + c];
                bf16add(a0, p0);
                bf16add(a1, p1);
                bf16add(a2, p2);
                bf16add(a3, p3);
            }
            for (; i < e; i++) bf16add(a0, Hb[g_csr[i] * 16 + c]);
            float dv = g_dis[node];
            float4 sf = ((const float4*)self)[node * 16 + c];
            float px = fmaf(dv, (a0.x + a1.x) + (a2.x + a3.x), sf.x);
            float py = fmaf(dv, (a0.y + a1.y) + (a2.y + a3.y), sf.y);
            float pz = fmaf(dv, (a0.z + a1.z) + (a2.z + a3.z), sf.z);
            float pw = fmaf(dv, (a0.w + a1.w) + (a2.w + a3.w), sf.w);
            sAggT[(4 * c + 0) * TS + nl] = px;
            sAggT[(4 * c + 1) * TS + nl] = py;
            sAggT[(4 * c + 2) * TS + nl] = pz;
            sAggT[(4 * c + 3) * TS + nl] = pw;
        }
    }
    __syncthreads();

    // ---- Phase 2: half-split FFMA2 GEMM (192 active threads) ----
    int rl = (tid < 96) ? tid : tid - 96;     // row local
    int h  = (tid < 96) ? 0 : 1;              // warp-uniform (warps 0-2 / 3-5)
    int row = base + rl;
    bool act = (tid < 192) && (row < N_NODES);

    float hres[32];
    if (act) {
        float svp = 1.f + g_dis[row] * g_svs[row];
        unsigned long long acc[16];
#pragma unroll
        for (int j = 0; j < 16; j++) {
            int cc = h * 32 + 2 * j;
            acc[j] = pack2(fmaf(svp, B2[cc],   B1[cc]),
                           fmaf(svp, B2[cc+1], B1[cc+1]));
        }
#pragma unroll 1
        for (int kk = 0; kk < 16; kk++) {
#pragma unroll
            for (int kc = 0; kc < 4; kc++) {
                float hk = sAggT[(kk * 4 + kc) * TS + rl];
                unsigned long long hk2 = pack2(hk, hk);
                const ulonglong2* wrow = (const ulonglong2*)(Ws2 + (kk * 4 + kc) * 32 + h * 16);
#pragma unroll
                for (int j = 0; j < 8; j++) {
                    ulonglong2 w = wrow[j];
                    ffma2(acc[2 * j],     hk2, w.x);
                    ffma2(acc[2 * j + 1], hk2, w.y);
                }
            }
        }
#pragma unroll
        for (int j = 0; j < 16; j++) {
            float lo, hi;
            unpack2(acc[j], lo, hi);
            hres[2*j]   = fmaxf(lo, 0.f);
            hres[2*j+1] = fmaxf(hi, 0.f);
        }
    } else {
#pragma unroll
        for (int j = 0; j < 32; j++) hres[j] = 0.f;
    }

    if (!final_layer) {
        if (act) {
            float dis = g_dis[row];
            unsigned int* HbW = rb ? g_Hb0 : g_Hb1;    // write OTHER buffer
            float4* o32 = (float4*)(g_Henc + row * DIM) + h * 8;
            uint2*  ob  = (uint2*)(HbW + row * (DIM/2)) + h * 8;
#pragma unroll
            for (int j = 0; j < 8; j++) {
                float a = hres[4*j], b = hres[4*j+1], cc = hres[4*j+2], d = hres[4*j+3];
                o32[j] = make_float4(a, b, cc, d);
                __nv_bfloat162 b0 = __floats2bfloat162_rn(a * dis, b * dis);
                __nv_bfloat162 b1 = __floats2bfloat162_rn(cc * dis, d * dis);
                ob[j] = make_uint2(*(unsigned int*)&b0, *(unsigned int*)&b1);
            }
        }
    } else {
        // readout: butterfly-reduce 32 cols across each (h-uniform) warp
        int lane = tid & 31;
        if (tid < 192) {
#pragma unroll
            for (int j = 0; j < 32; j++) {
                float v = hres[j];
#pragma unroll
                for (int o = 16; o; o >>= 1) v += __shfl_xor_sync(0xffffffffu, v, o);
                if (lane == 0) atomicAdd(&ssum[h * 32 + j], v);
            }
        }
        __syncthreads();
        if (tid < 64) atomicAdd(&g_sum64[tid], ssum[tid]);

        __threadfence();
        __shared__ int isLast;
        if (tid == 0) {
            int p = atomicAdd(&g_done, 1);
            isLast = (p == (int)gridDim.x - 1) ? 1 : 0;
        }
        __syncthreads();
        if (isLast && tid < 32) {
            float p = g_sum64[tid] * out_w[tid] + g_sum64[tid + 32] * out_w[tid + 32];
#pragma unroll
            for (int o = 16; o; o >>= 1) p += __shfl_down_sync(0xffffffffu, p, o);
            if (tid == 0) out[0] = p / (float)N_NODES + out_b[0];
        }
    }
}

// ---------------------------------------------------------------------------
extern "C" void kernel_launch(void* const* d_in, const int* in_sizes, int n_in,
                              void* d_out, int out_size)
{
    const float* H  = (const float*)d_in[0];
    const void*  ei = d_in[1];
    // d_in[2] = E (unused by reference GCN path)
    const float* enc_w[3] = {(const float*)d_in[3],  (const float*)d_in[7],  (const float*)d_in[11]};
    const float* enc_b[3] = {(const float*)d_in[4],  (const float*)d_in[8],  (const float*)d_in[12]};
    const float* upd_w[3] = {(const float*)d_in[5],  (const float*)d_in[9],  (const float*)d_in[13]};
    const float* upd_b[3] = {(const float*)d_in[6],  (const float*)d_in[10], (const float*)d_in[14]};
    const float* out_w = (const float*)d_in[15];
    const float* out_b = (const float*)d_in[16];
    float* out = (float*)d_out;

    const int EB  = (N_EDGES + 255) / 256;            // 4688
    const int PB  = (N_EDGES / 2 + 255) / 256;        // 2344
    const int NB  = (N_NODES + 255) / 256;            // 196
    const int AB  = (N_NODES * 16 + 255) / 256;       // 3125
    const int LB  = (N_NODES + NPB - 1) / NPB;        // 521

    k_init <<<NB, 256>>>((const unsigned long long*)ei,
                         enc_w[0], enc_b[0], upd_w[0],
                         enc_w[1], enc_b[1], upd_w[1],
                         enc_w[2], enc_b[2], upd_w[2]);
    k_prep <<<PB, 256>>>(ei);
    k_bsum <<<SCAN_B, 1024>>>();
    k_scan2<<<SCAN_B, 1024>>>();
    k_fillhb<<<EB + AB, 256>>>(H);

    // rb: layer0 reads buf0 (writes buf1); layer1 reads buf1 (writes buf0);
    // layer2 reads buf0 (no write).
    k_agglayer<<<LB, 256>>>(0, 1, 0, 0, H, upd_b[0], nullptr, nullptr, nullptr);
    k_agglayer<<<LB, 256>>>(1, 0, 0, 1, H, upd_b[1], nullptr, nullptr, nullptr);
    k_agglayer<<<LB, 256>>>(2, 0, 1, 0, H, upd_b[2], out_w, out_b, out);
}

// round 17
// speedup vs baseline: 1.2411x; 1.2411x over previous
#include <cuda_runtime.h>
#include <cuda_bf16.h>

#define N_NODES 50000
#define N_EDGES 1200000
#define DIM 64
#define SCAN_B 49   // ceil(50000/1024)

// Scratch (allocation-free __device__ globals)
__device__ __align__(16) float g_Henc[N_NODES * DIM];        // layer output H_l (fp32)
__device__ __align__(16) unsigned int g_Hb[N_NODES * DIM/2]; // bf16x2 of dis[u]*H_l[u]
__device__ __align__(16) float g_agg [N_NODES * DIM];        // P = (S+I)H
__device__ __align__(16) int   g_deg [N_NODES];              // out-degree over u
__device__ __align__(16) int   g_cnt [N_NODES];              // in-degree over v
__device__ __align__(16) int   g_rowstart[N_NODES + 1];      // CSR row offsets (by v)
__device__ __align__(16) int2  g_uv  [N_EDGES];              // decoded (u,v)
__device__ __align__(16) int   g_rank[N_EDGES];              // rank of edge within row v
__device__ __align__(16) int   g_csr [N_EDGES];              // u sorted by v
__device__ __align__(16) float g_dis [N_NODES];              // rsqrt(deg+1)
__device__ __align__(16) float g_svs [N_NODES];              // sum_{u in N(v)} dis_u
__device__ __align__(16) float g_Wc  [3 * DIM * DIM];        // composite We@Wu per layer
__device__ __align__(16) float g_c2  [3 * DIM];              // be@Wu per layer
__device__ __align__(16) float g_sum64[DIM];
__device__ __align__(16) int   g_bsum[SCAN_B];               // per-block cnt sums
__device__ int g_is32;   // 1 if edge_index is int32 on device
__device__ int g_done;   // last-block ticket for fused readout

// ---------------------------------------------------------------------------
// Packed f32x2 helpers
__device__ __forceinline__ void ffma2(unsigned long long& d,
                                      unsigned long long a,
                                      unsigned long long b) {
    asm("fma.rn.f32x2 %0, %1, %2, %0;" : "+l"(d) : "l"(a), "l"(b));
}
__device__ __forceinline__ unsigned long long pack2(float lo, float hi) {
    unsigned long long r;
    asm("mov.b64 %0, {%1, %2};" : "=l"(r) : "f"(lo), "f"(hi));
    return r;
}
__device__ __forceinline__ void unpack2(unsigned long long v, float& lo, float& hi) {
    asm("mov.b64 {%0, %1}, %2;" : "=f"(lo), "=f"(hi) : "l"(v));
}

// ---------------------------------------------------------------------------
// Init + weight composition + dtype probe (merged).
// Blocks 0-2: Wc_l = We_l@Wu_l, c2_l = be_l@Wu_l. Block 3: dtype probe.
__global__ void __launch_bounds__(256) k_init(
    const unsigned long long* __restrict__ ei,
    const float* __restrict__ We0, const float* __restrict__ Be0, const float* __restrict__ Wu0,
    const float* __restrict__ We1, const float* __restrict__ Be1, const float* __restrict__ Wu1,
    const float* __restrict__ We2, const float* __restrict__ Be2, const float* __restrict__ Wu2)
{
    int i = blockIdx.x * 256 + threadIdx.x;
    if (i < N_NODES) { g_deg[i] = 0; g_cnt[i] = 0; g_svs[i] = 0.f; }
    if (i < DIM)     g_sum64[i] = 0.f;
    if (i == 0)      g_done = 0;

    int b = blockIdx.x;
    int t = threadIdx.x;
    if (b == 3) {
        unsigned int any = 0;
        for (int j = t; j < 2048; j += 256)
            any |= (unsigned int)(ei[j] >> 32);
        __shared__ unsigned int s;
        if (t == 0) s = 0u;
        __syncthreads();
        atomicOr(&s, any);
        __syncthreads();
        if (t == 0) g_is32 = (s != 0u) ? 1 : 0;
    } else if (b < 3) {
        const float* We = (b == 0) ? We0 : (b == 1) ? We1 : We2;
        const float* Be = (b == 0) ? Be0 : (b == 1) ? Be1 : Be2;
        const float* Wu = (b == 0) ? Wu0 : (b == 1) ? Wu1 : Wu2;
        __shared__ float sWe[DIM * DIM], sWu[DIM * DIM];
        for (int j = t; j < DIM * DIM; j += 256) { sWe[j] = We[j]; sWu[j] = Wu[j]; }
        __syncthreads();
        for (int o = t; o < DIM * DIM; o += 256) {
            int r = o >> 6, c = o & 63;
            float acc = 0.f;
#pragma unroll 8
            for (int k = 0; k < DIM; k++)
                acc = fmaf(sWe[r * DIM + k], sWu[k * DIM + c], acc);
            g_Wc[b * DIM * DIM + o] = acc;
        }
        if (t < DIM) {
            float acc = 0.f;
#pragma unroll 8
            for (int k = 0; k < DIM; k++)
                acc = fmaf(Be[k], sWu[k * DIM + t], acc);
            g_c2[b * DIM + t] = acc;
        }
    }
}

// Decode edge index -> uv + rank, histogram deg(u)/cnt(v). 2 edges per thread.
__global__ void __launch_bounds__(256) k_prep(const void* __restrict__ eiv) {
    int p = blockIdx.x * 256 + threadIdx.x;       // pair index
    int i = p * 2;
    if (i >= N_EDGES) return;
    int u0, u1, v0, v1;
    if (g_is32) {
        const int2* e = (const int2*)eiv;
        int2 up = e[p];
        int2 vp = ((const int2*)((const int*)eiv + N_EDGES))[p];
        u0 = up.x; u1 = up.y; v0 = vp.x; v1 = vp.y;
    } else {
        const longlong2* e = (const longlong2*)eiv;
        longlong2 up = e[p];
        longlong2 vp = ((const longlong2*)((const long long*)eiv + N_EDGES))[p];
        u0 = (int)up.x; u1 = (int)up.y; v0 = (int)vp.x; v1 = (int)vp.y;
    }
    u0 = min(max(u0, 0), N_NODES - 1); u1 = min(max(u1, 0), N_NODES - 1);
    v0 = min(max(v0, 0), N_NODES - 1); v1 = min(max(v1, 0), N_NODES - 1);
    ((int4*)g_uv)[p] = make_int4(u0, v0, u1, v1);
    atomicAdd(&g_deg[u0], 1);
    atomicAdd(&g_deg[u1], 1);
    int r0 = atomicAdd(&g_cnt[v0], 1);
    int r1 = atomicAdd(&g_cnt[v1], 1);
    ((int2*)g_rank)[p] = make_int2(r0, r1);
}

// Per-block sums of g_cnt; also precompute dis = rsqrt(deg+1)
__global__ void __launch_bounds__(1024) k_bsum() {
    int t = threadIdx.x;
    int i = blockIdx.x * 1024 + t;
    int val = 0;
    if (i < N_NODES) {
        val = g_cnt[i];
        g_dis[i] = rsqrtf((float)g_deg[i] + 1.0f);
    }
#pragma unroll
    for (int o = 16; o; o >>= 1) val += __shfl_xor_sync(0xffffffffu, val, o);
    __shared__ int ws[32];
    if ((t & 31) == 0) ws[t >> 5] = val;
    __syncthreads();
    if (t < 32) {
        int v = ws[t];
#pragma unroll
        for (int o = 16; o; o >>= 1) v += __shfl_xor_sync(0xffffffffu, v, o);
        if (t == 0) g_bsum[blockIdx.x] = v;
    }
}

// Block-local exclusive scan + parallel-loaded global base -> g_rowstart
__global__ void __launch_bounds__(1024) k_scan2() {
    int t = threadIdx.x;
    int b = blockIdx.x;
    int i = b * 1024 + t;
    __shared__ int sbase;
    __shared__ int sb[SCAN_B];
    __shared__ int ws[32];
    if (t < SCAN_B) sb[t] = g_bsum[t];     // parallel load (no serial-LDG chain)
    __syncthreads();
    if (t == 0) {
        int a = 0;
        for (int j = 0; j < b; j++) a += sb[j];
        sbase = a;
    }
    int orig = (i < N_NODES) ? g_cnt[i] : 0;
    int val = orig;
    int lane = t & 31;
#pragma unroll
    for (int o = 1; o < 32; o <<= 1) {
        int n = __shfl_up_sync(0xffffffffu, val, o);
        if (lane >= o) val += n;
    }
    if (lane == 31) ws[t >> 5] = val;
    __syncthreads();
    if (t < 32) {
        int v = ws[t];
#pragma unroll
        for (int o = 1; o < 32; o <<= 1) {
            int n = __shfl_up_sync(0xffffffffu, v, o);
            if (t >= o) v += n;
        }
        ws[t] = v;
    }
    __syncthreads();
    int woff = (t >= 32) ? ws[(t >> 5) - 1] : 0;
    int excl = sbase + woff + (val - orig);
    if (i < N_NODES) {
        g_rowstart[i] = excl;
        if (i == N_NODES - 1) g_rowstart[N_NODES] = excl + orig;
    }
}

// Merged: CSR fill + svs accumulation (blocks < EB) + layer-0 Hb table (blocks >= EB).
#define EB_CONST ((N_EDGES + 255) / 256)
__global__ void __launch_bounds__(256) k_fillhb(const float* __restrict__ X) {
    int b = blockIdx.x;
    int t = threadIdx.x;
    if (b < EB_CONST) {
        int i = b * 256 + t;
        if (i >= N_EDGES) return;
        int2 uv = g_uv[i];
        int pos = g_rowstart[uv.y] + g_rank[i];
        g_csr[pos] = uv.x;
        atomicAdd(&g_svs[uv.y], g_dis[uv.x]);
    } else {
        int idx = (b - EB_CONST) * 256 + t;      // node*16 + c
        if (idx >= N_NODES * 16) return;
        int node = idx >> 4;
        float dis = g_dis[node];
        float4 v = ((const float4*)X)[idx];
        __nv_bfloat162 b0 = __floats2bfloat162_rn(v.x * dis, v.y * dis);
        __nv_bfloat162 b1 = __floats2bfloat162_rn(v.z * dis, v.w * dis);
        ((uint2*)g_Hb)[idx] = make_uint2(*(unsigned int*)&b0, *(unsigned int*)&b1);
    }
}

// ---------------------------------------------------------------------------
// bf16x2-pair add helper (dis_u pre-folded into Hb)
__device__ __forceinline__ void bf16add(float4& a, uint2 p) {
    float2 lo = __bfloat1622float2(*(__nv_bfloat162*)&p.x);
    float2 hi = __bfloat1622float2(*(__nv_bfloat162*)&p.y);
    a.x += lo.x; a.y += lo.y; a.z += hi.x; a.w += hi.y;
}

// Pull aggregation incl self: P[v] = dis_v * sum_e Hb[u_e] + self[v]
__global__ void __launch_bounds__(256) k_agg(const float* __restrict__ X, int use_gH) {
    int idx = blockIdx.x * 256 + threadIdx.x;
    int node = idx >> 4;
    if (node >= N_NODES) return;
    int c = idx & 15;
    int s = g_rowstart[node];
    int e = g_rowstart[node + 1];
    const uint2* __restrict__ Hb = (const uint2*)g_Hb;
    const float* self = use_gH ? g_Henc : X;

    float4 a0 = make_float4(0.f, 0.f, 0.f, 0.f);
    float4 a1 = make_float4(0.f, 0.f, 0.f, 0.f);
    float4 a2 = make_float4(0.f, 0.f, 0.f, 0.f);
    float4 a3 = make_float4(0.f, 0.f, 0.f, 0.f);

    int i = s;
    for (; i + 4 <= e; i += 4) {
        int u0 = g_csr[i];
        int u1 = g_csr[i + 1];
        int u2 = g_csr[i + 2];
        int u3 = g_csr[i + 3];
        uint2 p0 = Hb[u0 * 16 + c];
        uint2 p1 = Hb[u1 * 16 + c];
        uint2 p2 = Hb[u2 * 16 + c];
        uint2 p3 = Hb[u3 * 16 + c];
        bf16add(a0, p0);
        bf16add(a1, p1);
        bf16add(a2, p2);
        bf16add(a3, p3);
    }
    for (; i < e; i++) {
        uint2 p0 = Hb[g_csr[i] * 16 + c];
        bf16add(a0, p0);
    }

    float dv = g_dis[node];
    float4 sf = ((const float4*)self)[node * 16 + c];
    float4 acc;
    acc.x = fmaf(dv, (a0.x + a1.x) + (a2.x + a3.x), sf.x);
    acc.y = fmaf(dv, (a0.y + a1.y) + (a2.y + a3.y), sf.y);
    acc.z = fmaf(dv, (a0.z + a1.z) + (a2.z + a3.z), sf.z);
    acc.w = fmaf(dv, (a0.w + a1.w) + (a2.w + a3.w), sf.w);
    ((float4*)g_agg)[node * 16 + c] = acc;
}

// ---------------------------------------------------------------------------
// Layer GEMM core with FFMA2: row x (in-loop loads) @ Ws2 -> 32 packed acc.
__device__ __forceinline__ void gemm_f32x2(
    const float4* __restrict__ xr,
    const unsigned long long* __restrict__ Ws2,
    unsigned long long* __restrict__ acc)
{
#pragma unroll 1
    for (int kk = 0; kk < 16; kk++) {
        float4 hv = xr[kk];
#pragma unroll
        for (int kc = 0; kc < 4; kc++) {
            float hk = (kc == 0) ? hv.x : (kc == 1) ? hv.y : (kc == 2) ? hv.z : hv.w;
            unsigned long long hk2 = pack2(hk, hk);
            const ulonglong2* wrow = (const ulonglong2*)(Ws2 + (kk * 4 + kc) * 32);
#pragma unroll
            for (int j = 0; j < 16; j++) {
                ulonglong2 w = wrow[j];
                ffma2(acc[2 * j],     hk2, w.x);
                ffma2(acc[2 * j + 1], hk2, w.y);
            }
        }
    }
}

// Layer GEMM (one per layer): H' = relu(P @ Wc + bu + svp*c2), svp = 1+dis*svs.
__global__ void __launch_bounds__(128) k_layer(
    int l, const float* __restrict__ Bu)
{
    __shared__ unsigned long long Ws2[2048];   // 64 k x 32 pairs
    __shared__ float B1[64], B2[64];
    int tid = threadIdx.x;
    const ulonglong2* W8 = (const ulonglong2*)(g_Wc + l * DIM * DIM);
    ulonglong2* S8 = (ulonglong2*)Ws2;
#pragma unroll
    for (int i = 0; i < 8; i++) S8[tid + 128 * i] = W8[tid + 128 * i];
    if (tid < 64) { B1[tid] = Bu[tid]; B2[tid] = g_c2[l * DIM + tid]; }
    __syncthreads();

    int row = blockIdx.x * 128 + tid;
    if (row >= N_NODES) return;
    float dis = g_dis[row];
    float svp = 1.f + dis * g_svs[row];

    unsigned long long acc[32];
#pragma unroll
    for (int j = 0; j < 32; j++)
        acc[j] = pack2(fmaf(svp, B2[2*j],   B1[2*j]),
                       fmaf(svp, B2[2*j+1], B1[2*j+1]));

    gemm_f32x2((const float4*)(g_agg + row * DIM), Ws2, acc);

    float4* o32 = (float4*)(g_Henc + row * DIM);
    uint2*  ob  = (uint2*)(g_Hb + row * (DIM/2));
#pragma unroll
    for (int j = 0; j < 16; j++) {
        float a, b, c, d;
        unpack2(acc[2*j],     a, b);
        unpack2(acc[2*j + 1], c, d);
        a = fmaxf(a, 0.f); b = fmaxf(b, 0.f);
        c = fmaxf(c, 0.f); d = fmaxf(d, 0.f);
        o32[j] = make_float4(a, b, c, d);
        __nv_bfloat162 b0 = __floats2bfloat162_rn(a * dis, b * dis);
        __nv_bfloat162 b1 = __floats2bfloat162_rn(c * dis, d * dis);
        ob[j] = make_uint2(*(unsigned int*)&b0, *(unsigned int*)&b1);
    }
}

// Final layer GEMM + mean-readout + last-block finalize (FFMA2).
__global__ void __launch_bounds__(128) k_layer_sum(
    int l, const float* __restrict__ Bu,
    const float* __restrict__ out_w, const float* __restrict__ out_b,
    float* __restrict__ out)
{
    __shared__ unsigned long long Ws2[2048];
    __shared__ float B1[64], B2[64];
    __shared__ float ssum[64];
    int tid = threadIdx.x;
    const ulonglong2* W8 = (const ulonglong2*)(g_Wc + l * DIM * DIM);
    ulonglong2* S8 = (ulonglong2*)Ws2;
#pragma unroll
    for (int i = 0; i < 8; i++) S8[tid + 128 * i] = W8[tid + 128 * i];
    if (tid < 64) { B1[tid] = Bu[tid]; B2[tid] = g_c2[l * DIM + tid]; ssum[tid] = 0.f; }
    __syncthreads();

    int row = blockIdx.x * 128 + tid;
    bool valid = (row < N_NODES);

    float h[64];
    if (valid) {
        float svp = 1.f + g_dis[row] * g_svs[row];
        unsigned long long acc[32];
#pragma unroll
        for (int j = 0; j < 32; j++)
            acc[j] = pack2(fmaf(svp, B2[2*j],   B1[2*j]),
                           fmaf(svp, B2[2*j+1], B1[2*j+1]));
        gemm_f32x2((const float4*)(g_agg + row * DIM), Ws2, acc);
#pragma unroll
        for (int j = 0; j < 32; j++) {
            float lo, hi;
            unpack2(acc[j], lo, hi);
            h[2*j]   = fmaxf(lo, 0.f);
            h[2*j+1] = fmaxf(hi, 0.f);
        }
    } else {
#pragma unroll
        for (int j = 0; j < 64; j++) h[j] = 0.f;
    }

    int lane = tid & 31;
#pragma unroll
    for (int j = 0; j < 64; j++) {
        float v = h[j];
#pragma unroll
        for (int o = 16; o; o >>= 1) v += __shfl_xor_sync(0xffffffffu, v, o);
        if (lane == 0) atomicAdd(&ssum[j], v);
    }
    __syncthreads();
    if (tid < 64) atomicAdd(&g_sum64[tid], ssum[tid]);

    __threadfence();
    __shared__ int isLast;
    if (tid == 0) {
        int p = atomicAdd(&g_done, 1);
        isLast = (p == (int)gridDim.x - 1) ? 1 : 0;
    }
    __syncthreads();
    if (isLast && tid < 32) {
        float p = g_sum64[tid] * out_w[tid] + g_sum64[tid + 32] * out_w[tid + 32];
#pragma unroll
        for (int o = 16; o; o >>= 1) p += __shfl_down_sync(0xffffffffu, p, o);
        if (tid == 0) out[0] = p / (float)N_NODES + out_b[0];
    }
}

// ---------------------------------------------------------------------------
extern "C" void kernel_launch(void* const* d_in, const int* in_sizes, int n_in,
                              void* d_out, int out_size)
{
    const float* H  = (const float*)d_in[0];
    const void*  ei = d_in[1];
    // d_in[2] = E (unused by reference GCN path)
    const float* enc_w[3] = {(const float*)d_in[3],  (const float*)d_in[7],  (const float*)d_in[11]};
    const float* enc_b[3] = {(const float*)d_in[4],  (const float*)d_in[8],  (const float*)d_in[12]};
    const float* upd_w[3] = {(const float*)d_in[5],  (const float*)d_in[9],  (const float*)d_in[13]};
    const float* upd_b[3] = {(const float*)d_in[6],  (const float*)d_in[10], (const float*)d_in[14]};
    const float* out_w = (const float*)d_in[15];
    const float* out_b = (const float*)d_in[16];
    float* out = (float*)d_out;

    const int EB  = (N_EDGES + 255) / 256;            // 4688
    const int PB  = (N_EDGES / 2 + 255) / 256;        // 2344
    const int NB  = (N_NODES + 255) / 256;            // 196
    const int GB  = (N_NODES + 127) / 128;            // 391
    const int AB  = (N_NODES * 16 + 255) / 256;       // 3125

    k_init <<<NB, 256>>>((const unsigned long long*)ei,
                         enc_w[0], enc_b[0], upd_w[0],
                         enc_w[1], enc_b[1], upd_w[1],
                         enc_w[2], enc_b[2], upd_w[2]);
    k_prep <<<PB, 256>>>(ei);
    k_bsum <<<SCAN_B, 1024>>>();
    k_scan2<<<SCAN_B, 1024>>>();
    k_fillhb<<<EB + AB, 256>>>(H);

    k_agg  <<<AB, 256>>>(H, 0);              // P0 = (S+I)X
    k_layer<<<GB, 128>>>(0, upd_b[0]);       // H1
    k_agg  <<<AB, 256>>>(H, 1);              // P1 = (S+I)H1
    k_layer<<<GB, 128>>>(1, upd_b[1]);       // H2
    k_agg  <<<AB, 256>>>(H, 1);              // P2 = (S+I)H2
    k_layer_sum<<<GB, 128>>>(2, upd_b[2], out_w, out_b, out);
}